// round 13
// baseline (speedup 1.0000x reference)
#include <cuda_runtime.h>
#include <cuda_bf16.h>
#include <math.h>

// Problem constants (fixed by the reference: B=4, C=256, H=W=64, Co=32)
#define BB   4
#define CC   256
#define HW   4096          // N = H*W
#define CO   32
#define OUT_ELEMS (BB*CC*HW)   // 4,194,304 floats; attn follows in d_out

// Scratch: everything pre-split into bf16 hi/lo pairs
__device__ __nv_bfloat16 g_qh[BB * CO * HW];
__device__ __nv_bfloat16 g_ql[BB * CO * HW];
__device__ __nv_bfloat16 g_kh[BB * CO * HW];
__device__ __nv_bfloat16 g_kl[BB * CO * HW];
__device__ __nv_bfloat16 g_vh[BB * CC * HW];
__device__ __nv_bfloat16 g_vl[BB * CC * HW];
__device__ __nv_bfloat16 g_ah[(size_t)BB * HW * HW];   // attn hi (128 MB)
__device__ __nv_bfloat16 g_al[(size_t)BB * HW * HW];   // attn lo (128 MB)

__device__ __forceinline__ void split_bf16(float f, __nv_bfloat16& hi, __nv_bfloat16& lo)
{
    hi = __float2bfloat16(f);
    lo = __float2bfloat16(f - __bfloat162float(hi));
}

// ---------------------------------------------------------------------------
// 1x1 conv as GEMM: y[b,o,n] = sum_c W[o,c]*x[b,c,n] + bias[o] -> bf16 hi/lo
// ---------------------------------------------------------------------------
__global__ __launch_bounds__(256)
void conv1x1_kernel(const float* __restrict__ x, const float* __restrict__ W,
                    const float* __restrict__ bias,
                    __nv_bfloat16* __restrict__ yh, __nv_bfloat16* __restrict__ yl,
                    int O)
{
    const int b  = blockIdx.z;
    const int o0 = blockIdx.y * 64;
    const int n0 = blockIdx.x * 64;

    __shared__ float Ws[16][68];
    __shared__ float Xs[16][64];

    const int t  = threadIdx.x;
    const int ty = t >> 4;
    const int tx = t & 15;

    const float* xb = x + (size_t)b * CC * HW;
    float acc[4][4] = {};

    for (int k0 = 0; k0 < CC; k0 += 16) {
        {
            int o   = t >> 2;
            int kk4 = (t & 3) * 4;
            float4 w4 = make_float4(0.f, 0.f, 0.f, 0.f);
            if (o0 + o < O)
                w4 = *reinterpret_cast<const float4*>(&W[(size_t)(o0 + o) * CC + k0 + kk4]);
            Ws[kk4 + 0][o] = w4.x;
            Ws[kk4 + 1][o] = w4.y;
            Ws[kk4 + 2][o] = w4.z;
            Ws[kk4 + 3][o] = w4.w;
        }
        {
            int kk  = t >> 4;
            int nn4 = (t & 15) * 4;
            float4 x4 = *reinterpret_cast<const float4*>(&xb[(size_t)(k0 + kk) * HW + n0 + nn4]);
            *reinterpret_cast<float4*>(&Xs[kk][nn4]) = x4;
        }
        __syncthreads();

        #pragma unroll
        for (int kk = 0; kk < 16; kk++) {
            float a[4], bv_[4];
            #pragma unroll
            for (int i = 0; i < 4; i++) a[i]   = Ws[kk][ty * 4 + i];
            #pragma unroll
            for (int j = 0; j < 4; j++) bv_[j] = Xs[kk][tx * 4 + j];
            #pragma unroll
            for (int i = 0; i < 4; i++)
                #pragma unroll
                for (int j = 0; j < 4; j++)
                    acc[i][j] = fmaf(a[i], bv_[j], acc[i][j]);
        }
        __syncthreads();
    }

    #pragma unroll
    for (int i = 0; i < 4; i++) {
        int o = o0 + ty * 4 + i;
        if (o < O) {
            float bo = bias[o];
            __nv_bfloat16 h[4], l[4];
            #pragma unroll
            for (int j = 0; j < 4; j++)
                split_bf16(acc[i][j] + bo, h[j], l[j]);
            size_t base = (size_t)b * O * HW + (size_t)o * HW + n0 + tx * 4;
            *reinterpret_cast<__nv_bfloat162*>(&yh[base])     = __nv_bfloat162(h[0], h[1]);
            *reinterpret_cast<__nv_bfloat162*>(&yh[base + 2]) = __nv_bfloat162(h[2], h[3]);
            *reinterpret_cast<__nv_bfloat162*>(&yl[base])     = __nv_bfloat162(l[0], l[1]);
            *reinterpret_cast<__nv_bfloat162*>(&yl[base + 2]) = __nv_bfloat162(l[2], l[3]);
        }
    }
}

// ---------------------------------------------------------------------------
// mma / ldmatrix helpers
// ---------------------------------------------------------------------------
__device__ __forceinline__ void mma16816(float* c, const unsigned* a, const unsigned* b)
{
    asm volatile(
        "mma.sync.aligned.m16n8k16.row.col.f32.bf16.bf16.f32 "
        "{%0,%1,%2,%3}, {%4,%5,%6,%7}, {%8,%9}, {%0,%1,%2,%3};\n"
        : "+f"(c[0]), "+f"(c[1]), "+f"(c[2]), "+f"(c[3])
        : "r"(a[0]), "r"(a[1]), "r"(a[2]), "r"(a[3]), "r"(b[0]), "r"(b[1]));
}

__device__ __forceinline__ void ldm_x4(unsigned* r, const void* p)
{
    unsigned addr = (unsigned)__cvta_generic_to_shared(p);
    asm volatile("ldmatrix.sync.aligned.m8n8.x4.shared.b16 {%0,%1,%2,%3}, [%4];\n"
                 : "=r"(r[0]), "=r"(r[1]), "=r"(r[2]), "=r"(r[3]) : "r"(addr));
}

__device__ __forceinline__ void ldm_x4_trans(unsigned* r, const void* p)
{
    unsigned addr = (unsigned)__cvta_generic_to_shared(p);
    asm volatile("ldmatrix.sync.aligned.m8n8.x4.trans.shared.b16 {%0,%1,%2,%3}, [%4];\n"
                 : "=r"(r[0]), "=r"(r[1]), "=r"(r[2]), "=r"(r[3]) : "r"(addr));
}

// ---------------------------------------------------------------------------
// Fused scores + softmax + bf16-split kernel.
// One CTA per (b, 128-row n-block). 8 warps, each warp owns 16 rows.
// Pass 1: stream Q chunks (128 m), mma scores, online row max/sum (no store).
// Pass 2: recompute scores, write attn fp32 + bf16 hi/lo.
// K tile is fixed per CTA -> A-fragments (trans ldmatrix + {0,2,1,3} reorder,
// validated in R8 scores kernel) live in registers for the whole kernel.
// ---------------------------------------------------------------------------
__global__ __launch_bounds__(256)
void fused_attn_kernel(float* __restrict__ attn)
{
    const int b  = blockIdx.y;
    const int n0 = blockIdx.x * 128;

    __shared__ __nv_bfloat16 Ks_hi[32][136];
    __shared__ __nv_bfloat16 Ks_lo[32][136];
    __shared__ __nv_bfloat16 Qs_hi[32][136];
    __shared__ __nv_bfloat16 Qs_lo[32][136];

    const int t    = threadIdx.x;
    const int lane = t & 31;
    const int wid  = t >> 5;          // 0..7, warp owns rows n0 + wid*16 .. +15

    const __nv_bfloat16* kh = g_kh + (size_t)b * CO * HW;
    const __nv_bfloat16* kl = g_kl + (size_t)b * CO * HW;
    const __nv_bfloat16* qh = g_qh + (size_t)b * CO * HW;
    const __nv_bfloat16* ql = g_ql + (size_t)b * CO * HW;

    // Staging map (512 uint4 per 32x128 array, 2 per thread)
    const int st_r = t >> 4;              // 0..15, +16 for e=1
    const int st_g = (t & 15) * 8;

    // Stage K tile once
    #pragma unroll
    for (int e = 0; e < 2; e++) {
        int r = st_r + e * 16;
        *reinterpret_cast<uint4*>(&Ks_hi[r][st_g]) = *reinterpret_cast<const uint4*>(&kh[(size_t)r * HW + n0 + st_g]);
        *reinterpret_cast<uint4*>(&Ks_lo[r][st_g]) = *reinterpret_cast<const uint4*>(&kl[(size_t)r * HW + n0 + st_g]);
    }
    __syncthreads();

    // A-fragments for this warp's 16 rows (persist across both passes)
    unsigned aH[2][4], aL[2][4];
    #pragma unroll
    for (int s = 0; s < 2; s++) {
        unsigned tmp[4];
        int cr = s * 16 + (lane & 15);
        int nc = wid * 16 + (lane >> 4) * 8;
        ldm_x4_trans(tmp, &Ks_hi[cr][nc]);
        aH[s][0] = tmp[0]; aH[s][1] = tmp[2]; aH[s][2] = tmp[1]; aH[s][3] = tmp[3];
        ldm_x4_trans(tmp, &Ks_lo[cr][nc]);
        aL[s][0] = tmp[0]; aL[s][1] = tmp[2]; aL[s][2] = tmp[1]; aL[s][3] = tmp[3];
    }
    __syncthreads();   // done reading Ks via ldmatrix before Qs reuse? (Ks distinct; just order safety)

    float m0 = -1e30f, m1 = -1e30f;   // running row max (rows r0, r0+8)
    float l0 = 0.f,    l1 = 0.f;      // running row sum of exp

    uint4 pq_h[2], pq_l[2];
    float acc[16][4];

    // ---- helper macros for chunk staging + compute ----
#define STAGE_STORE()                                                              \
    {                                                                              \
        _Pragma("unroll")                                                          \
        for (int e = 0; e < 2; e++) {                                              \
            int r = st_r + e * 16;                                                 \
            *reinterpret_cast<uint4*>(&Qs_hi[r][st_g]) = pq_h[e];                  \
            *reinterpret_cast<uint4*>(&Qs_lo[r][st_g]) = pq_l[e];                  \
        }                                                                          \
    }

#define STAGE_PREFETCH(moff)                                                       \
    {                                                                              \
        _Pragma("unroll")                                                          \
        for (int e = 0; e < 2; e++) {                                              \
            int r = st_r + e * 16;                                                 \
            pq_h[e] = *reinterpret_cast<const uint4*>(&qh[(size_t)r * HW + (moff) + st_g]); \
            pq_l[e] = *reinterpret_cast<const uint4*>(&ql[(size_t)r * HW + (moff) + st_g]); \
        }                                                                          \
    }

#define COMPUTE_CHUNK()                                                            \
    {                                                                              \
        _Pragma("unroll")                                                          \
        for (int nt = 0; nt < 16; nt++) {                                          \
            acc[nt][0] = 0.f; acc[nt][1] = 0.f; acc[nt][2] = 0.f; acc[nt][3] = 0.f;\
        }                                                                          \
        _Pragma("unroll")                                                          \
        for (int s = 0; s < 2; s++) {                                              \
            _Pragma("unroll")                                                      \
            for (int nj = 0; nj < 8; nj++) {                                       \
                unsigned bh[4], bl[4];                                             \
                int cr = s * 16 + (lane & 15);                                     \
                int mc = nj * 16 + (lane >> 4) * 8;                                \
                ldm_x4_trans(bh, &Qs_hi[cr][mc]);                                  \
                ldm_x4_trans(bl, &Qs_lo[cr][mc]);                                  \
                _Pragma("unroll")                                                  \
                for (int h = 0; h < 2; h++) {                                      \
                    mma16816(acc[nj * 2 + h], aH[s], &bh[h * 2]);                  \
                    mma16816(acc[nj * 2 + h], aL[s], &bh[h * 2]);                  \
                    mma16816(acc[nj * 2 + h], aH[s], &bl[h * 2]);                  \
                }                                                                  \
            }                                                                      \
        }                                                                          \
    }

    // =================== PASS 1: row max + sum ===================
    STAGE_PREFETCH(0);
    for (int ch = 0; ch < 32; ch++) {
        STAGE_STORE();
        __syncthreads();
        int mnext = (ch + 1 < 32) ? (ch + 1) * 128 : 0;
        STAGE_PREFETCH(mnext);
        COMPUTE_CHUNK();
        __syncthreads();

        // chunk row max (rows r0 and r0+8)
        float cm0 = -1e30f, cm1 = -1e30f;
        #pragma unroll
        for (int nt = 0; nt < 16; nt++) {
            cm0 = fmaxf(cm0, fmaxf(acc[nt][0], acc[nt][1]));
            cm1 = fmaxf(cm1, fmaxf(acc[nt][2], acc[nt][3]));
        }
        cm0 = fmaxf(cm0, __shfl_xor_sync(0xffffffffu, cm0, 1));
        cm0 = fmaxf(cm0, __shfl_xor_sync(0xffffffffu, cm0, 2));
        cm1 = fmaxf(cm1, __shfl_xor_sync(0xffffffffu, cm1, 1));
        cm1 = fmaxf(cm1, __shfl_xor_sync(0xffffffffu, cm1, 2));

        float mn0 = fmaxf(m0, cm0);
        float mn1 = fmaxf(m1, cm1);

        float s0 = 0.f, s1 = 0.f;
        #pragma unroll
        for (int nt = 0; nt < 16; nt++) {
            s0 += __expf(acc[nt][0] - mn0) + __expf(acc[nt][1] - mn0);
            s1 += __expf(acc[nt][2] - mn1) + __expf(acc[nt][3] - mn1);
        }
        s0 += __shfl_xor_sync(0xffffffffu, s0, 1);
        s0 += __shfl_xor_sync(0xffffffffu, s0, 2);
        s1 += __shfl_xor_sync(0xffffffffu, s1, 1);
        s1 += __shfl_xor_sync(0xffffffffu, s1, 2);

        l0 = l0 * __expf(m0 - mn0) + s0;
        l1 = l1 * __expf(m1 - mn1) + s1;
        m0 = mn0;
        m1 = mn1;
    }

    const float inv0 = 1.0f / l0;
    const float inv1 = 1.0f / l1;

    // =================== PASS 2: recompute + write ===================
    const int row0 = wid * 16 + (lane >> 2);
    float* Ab = attn + (size_t)b * HW * HW;
    __nv_bfloat16* AHb = g_ah + (size_t)b * HW * HW;
    __nv_bfloat16* ALb = g_al + (size_t)b * HW * HW;
    const size_t r0base = (size_t)(n0 + row0) * HW;
    const size_t r1base = (size_t)(n0 + row0 + 8) * HW;

    STAGE_PREFETCH(0);
    for (int ch = 0; ch < 32; ch++) {
        STAGE_STORE();
        __syncthreads();
        int mnext = (ch + 1 < 32) ? (ch + 1) * 128 : 0;
        STAGE_PREFETCH(mnext);
        COMPUTE_CHUNK();
        __syncthreads();

        #pragma unroll
        for (int nt = 0; nt < 16; nt++) {
            int col = ch * 128 + nt * 8 + (lane & 3) * 2;
            float p0 = __expf(acc[nt][0] - m0) * inv0;
            float p1 = __expf(acc[nt][1] - m0) * inv0;
            float p2 = __expf(acc[nt][2] - m1) * inv1;
            float p3 = __expf(acc[nt][3] - m1) * inv1;

            *reinterpret_cast<float2*>(&Ab[r0base + col]) = make_float2(p0, p1);
            *reinterpret_cast<float2*>(&Ab[r1base + col]) = make_float2(p2, p3);

            __nv_bfloat16 h0, lo0, h1, lo1, h2, lo2, h3, lo3;
            split_bf16(p0, h0, lo0);
            split_bf16(p1, h1, lo1);
            split_bf16(p2, h2, lo2);
            split_bf16(p3, h3, lo3);
            *reinterpret_cast<__nv_bfloat162*>(&AHb[r0base + col]) = __nv_bfloat162(h0, h1);
            *reinterpret_cast<__nv_bfloat162*>(&AHb[r1base + col]) = __nv_bfloat162(h2, h3);
            *reinterpret_cast<__nv_bfloat162*>(&ALb[r0base + col]) = __nv_bfloat162(lo0, lo1);
            *reinterpret_cast<__nv_bfloat162*>(&ALb[r1base + col]) = __nv_bfloat162(lo2, lo3);
        }
    }
#undef STAGE_STORE
#undef STAGE_PREFETCH
#undef COMPUTE_CHUNK
}

// ---------------------------------------------------------------------------
// Tensor-core AV (exact R8 config — best measured).
// out[b,c,m] = gamma * sum_n v[b,c,n]*attn[b,n,m] + x[b,c,m]
// Block 128(c) x 128(m), BK=32, 8 warps, warp tile 64x32, register prefetch.
// ---------------------------------------------------------------------------
__global__ __launch_bounds__(256)
void av_mma_kernel(const float* __restrict__ x, const float* __restrict__ gamma,
                   float* __restrict__ out)
{
    const int b  = blockIdx.z;
    const int c0 = blockIdx.y * 128;
    const int m0 = blockIdx.x * 128;

    __shared__ __nv_bfloat16 As_hi[128][40];
    __shared__ __nv_bfloat16 As_lo[128][40];
    __shared__ __nv_bfloat16 Bs_hi[32][136];
    __shared__ __nv_bfloat16 Bs_lo[32][136];

    const __nv_bfloat16* Ah = g_vh + (size_t)b * CC * HW;
    const __nv_bfloat16* Al = g_vl + (size_t)b * CC * HW;
    const __nv_bfloat16* Bh = g_ah + (size_t)b * HW * HW;
    const __nv_bfloat16* Bl = g_al + (size_t)b * HW * HW;

    const int t    = threadIdx.x;
    const int lane = t & 31;
    const int wid  = t >> 5;
    const int wm   = wid >> 2;
    const int wn   = wid & 3;

    const int a_row = t >> 2;
    const int a_kc  = (t & 3) * 8;
    const int b_row = t >> 4;
    const int b_mc  = (t & 15) * 8;

    float c[4][4][4];
    #pragma unroll
    for (int i = 0; i < 4; i++)
        #pragma unroll
        for (int j = 0; j < 4; j++)
            #pragma unroll
            for (int e = 0; e < 4; e++) c[i][j][e] = 0.f;

    uint4 pa_h[2], pa_l[2], pb_h[2], pb_l[2];
    #pragma unroll
    for (int e = 0; e < 2; e++) {
        pa_h[e] = *reinterpret_cast<const uint4*>(&Ah[(size_t)(c0 + a_row + e * 64) * HW + a_kc]);
        pa_l[e] = *reinterpret_cast<const uint4*>(&Al[(size_t)(c0 + a_row + e * 64) * HW + a_kc]);
        pb_h[e] = *reinterpret_cast<const uint4*>(&Bh[(size_t)(b_row + e * 16) * HW + m0 + b_mc]);
        pb_l[e] = *reinterpret_cast<const uint4*>(&Bl[(size_t)(b_row + e * 16) * HW + m0 + b_mc]);
    }

    for (int k0 = 0; k0 < HW; k0 += 32) {
        #pragma unroll
        for (int e = 0; e < 2; e++) {
            *reinterpret_cast<uint4*>(&As_hi[a_row + e * 64][a_kc]) = pa_h[e];
            *reinterpret_cast<uint4*>(&As_lo[a_row + e * 64][a_kc]) = pa_l[e];
            *reinterpret_cast<uint4*>(&Bs_hi[b_row + e * 16][b_mc]) = pb_h[e];
            *reinterpret_cast<uint4*>(&Bs_lo[b_row + e * 16][b_mc]) = pb_l[e];
        }
        __syncthreads();

        int kn = (k0 + 32 < HW) ? (k0 + 32) : 0;
        #pragma unroll
        for (int e = 0; e < 2; e++) {
            pa_h[e] = *reinterpret_cast<const uint4*>(&Ah[(size_t)(c0 + a_row + e * 64) * HW + kn + a_kc]);
            pa_l[e] = *reinterpret_cast<const uint4*>(&Al[(size_t)(c0 + a_row + e * 64) * HW + kn + a_kc]);
            pb_h[e] = *reinterpret_cast<const uint4*>(&Bh[(size_t)(kn + b_row + e * 16) * HW + m0 + b_mc]);
            pb_l[e] = *reinterpret_cast<const uint4*>(&Bl[(size_t)(kn + b_row + e * 16) * HW + m0 + b_mc]);
        }

        #pragma unroll
        for (int s = 0; s < 2; s++) {
            unsigned ah[4][4], al[4][4];
            #pragma unroll
            for (int mi = 0; mi < 4; mi++) {
                int ar = wm * 64 + mi * 16 + (lane & 15);
                int ac = s * 16 + (lane >> 4) * 8;
                ldm_x4(ah[mi], &As_hi[ar][ac]);
                ldm_x4(al[mi], &As_lo[ar][ac]);
            }
            unsigned bh[2][4], bl[2][4];
            #pragma unroll
            for (int nj = 0; nj < 2; nj++) {
                int br = s * 16 + (lane & 15);
                int bc = wn * 32 + nj * 16 + (lane >> 4) * 8;
                ldm_x4_trans(bh[nj], &Bs_hi[br][bc]);
                ldm_x4_trans(bl[nj], &Bs_lo[br][bc]);
            }
            #pragma unroll
            for (int mi = 0; mi < 4; mi++) {
                #pragma unroll
                for (int nt = 0; nt < 4; nt++) {
                    const unsigned* bfh = &bh[nt >> 1][(nt & 1) * 2];
                    const unsigned* bfl = &bl[nt >> 1][(nt & 1) * 2];
                    mma16816(c[mi][nt], ah[mi], bfh);   // hi*hi
                    mma16816(c[mi][nt], al[mi], bfh);   // lo*hi
                    mma16816(c[mi][nt], ah[mi], bfl);   // hi*lo
                }
            }
        }
        __syncthreads();
    }

    const float g = gamma[0];
    const float* xb = x   + (size_t)b * CC * HW;
    float*       ob = out + (size_t)b * CC * HW;
    #pragma unroll
    for (int mi = 0; mi < 4; mi++) {
        #pragma unroll
        for (int nt = 0; nt < 4; nt++) {
            int r   = c0 + wm * 64 + mi * 16 + (lane >> 2);
            int col = m0 + wn * 32 + nt * 8 + (lane & 3) * 2;
            const float* cc = c[mi][nt];
            size_t i0 = (size_t)r * HW + col;
            float2 x0 = *reinterpret_cast<const float2*>(&xb[i0]);
            float2 o0;
            o0.x = fmaf(g, cc[0], x0.x);
            o0.y = fmaf(g, cc[1], x0.y);
            *reinterpret_cast<float2*>(&ob[i0]) = o0;
            size_t i1 = (size_t)(r + 8) * HW + col;
            float2 x1 = *reinterpret_cast<const float2*>(&xb[i1]);
            float2 o1;
            o1.x = fmaf(g, cc[2], x1.x);
            o1.y = fmaf(g, cc[3], x1.y);
            *reinterpret_cast<float2*>(&ob[i1]) = o1;
        }
    }
}

// ---------------------------------------------------------------------------
extern "C" void kernel_launch(void* const* d_in, const int* in_sizes, int n_in,
                              void* d_out, int out_size)
{
    (void)in_sizes; (void)n_in; (void)out_size;
    const float* x     = (const float*)d_in[0];
    const float* Wq    = (const float*)d_in[1];
    const float* bq    = (const float*)d_in[2];
    const float* Wk    = (const float*)d_in[3];
    const float* bk    = (const float*)d_in[4];
    const float* Wv    = (const float*)d_in[5];
    const float* bv    = (const float*)d_in[6];
    const float* gamma = (const float*)d_in[7];

    float* out  = (float*)d_out;
    float* attn = out + (size_t)OUT_ELEMS;

    __nv_bfloat16 *qh, *ql, *kh, *kl, *vh, *vl;
    cudaGetSymbolAddress((void**)&qh, g_qh);
    cudaGetSymbolAddress((void**)&ql, g_ql);
    cudaGetSymbolAddress((void**)&kh, g_kh);
    cudaGetSymbolAddress((void**)&kl, g_kl);
    cudaGetSymbolAddress((void**)&vh, g_vh);
    cudaGetSymbolAddress((void**)&vl, g_vl);

    // QKV projections -> bf16 hi/lo
    {
        dim3 blk(256);
        dim3 grid_qk(HW / 64, 1, BB);
        dim3 grid_v (HW / 64, CC / 64, BB);
        conv1x1_kernel<<<grid_qk, blk>>>(x, Wq, bq, qh, ql, CO);
        conv1x1_kernel<<<grid_qk, blk>>>(x, Wk, bk, kh, kl, CO);
        conv1x1_kernel<<<grid_v,  blk>>>(x, Wv, bv, vh, vl, CC);
    }

    // Fused scores + softmax + bf16 split: writes attn fp32 + g_ah/g_al
    {
        dim3 blk(256);
        dim3 grid(HW / 128, BB);
        fused_attn_kernel<<<grid, blk>>>(attn);
    }

    // out = gamma * (V @ attn) + x on tensor cores (R8 config)
    {
        dim3 blk(256);
        dim3 grid(HW / 128, CC / 128, BB);
        av_mma_kernel<<<grid, blk>>>(x, gamma, out);
    }
}

// round 14
// speedup vs baseline: 1.1925x; 1.1925x over previous
#include <cuda_runtime.h>
#include <cuda_bf16.h>
#include <math.h>

// Problem constants (fixed by the reference: B=4, C=256, H=W=64, Co=32)
#define BB   4
#define CC   256
#define HW   4096          // N = H*W
#define CO   32
#define OUT_ELEMS (BB*CC*HW)   // 4,194,304 floats; attn follows in d_out

// Scratch: q/k/v pre-split into bf16 hi/lo pairs (attn stays fp32 in d_out)
__device__ __nv_bfloat16 g_qh[BB * CO * HW];
__device__ __nv_bfloat16 g_ql[BB * CO * HW];
__device__ __nv_bfloat16 g_kh[BB * CO * HW];
__device__ __nv_bfloat16 g_kl[BB * CO * HW];
__device__ __nv_bfloat16 g_vh[BB * CC * HW];
__device__ __nv_bfloat16 g_vl[BB * CC * HW];

__device__ __forceinline__ void split_bf16(float f, __nv_bfloat16& hi, __nv_bfloat16& lo)
{
    hi = __float2bfloat16(f);
    lo = __float2bfloat16(f - __bfloat162float(hi));
}

// ---------------------------------------------------------------------------
// 1x1 conv as GEMM: y[b,o,n] = sum_c W[o,c]*x[b,c,n] + bias[o] -> bf16 hi/lo
// ---------------------------------------------------------------------------
__global__ __launch_bounds__(256)
void conv1x1_kernel(const float* __restrict__ x, const float* __restrict__ W,
                    const float* __restrict__ bias,
                    __nv_bfloat16* __restrict__ yh, __nv_bfloat16* __restrict__ yl,
                    int O)
{
    const int b  = blockIdx.z;
    const int o0 = blockIdx.y * 64;
    const int n0 = blockIdx.x * 64;

    __shared__ float Ws[16][68];
    __shared__ float Xs[16][64];

    const int t  = threadIdx.x;
    const int ty = t >> 4;
    const int tx = t & 15;

    const float* xb = x + (size_t)b * CC * HW;
    float acc[4][4] = {};

    for (int k0 = 0; k0 < CC; k0 += 16) {
        {
            int o   = t >> 2;
            int kk4 = (t & 3) * 4;
            float4 w4 = make_float4(0.f, 0.f, 0.f, 0.f);
            if (o0 + o < O)
                w4 = *reinterpret_cast<const float4*>(&W[(size_t)(o0 + o) * CC + k0 + kk4]);
            Ws[kk4 + 0][o] = w4.x;
            Ws[kk4 + 1][o] = w4.y;
            Ws[kk4 + 2][o] = w4.z;
            Ws[kk4 + 3][o] = w4.w;
        }
        {
            int kk  = t >> 4;
            int nn4 = (t & 15) * 4;
            float4 x4 = *reinterpret_cast<const float4*>(&xb[(size_t)(k0 + kk) * HW + n0 + nn4]);
            *reinterpret_cast<float4*>(&Xs[kk][nn4]) = x4;
        }
        __syncthreads();

        #pragma unroll
        for (int kk = 0; kk < 16; kk++) {
            float a[4], bv_[4];
            #pragma unroll
            for (int i = 0; i < 4; i++) a[i]   = Ws[kk][ty * 4 + i];
            #pragma unroll
            for (int j = 0; j < 4; j++) bv_[j] = Xs[kk][tx * 4 + j];
            #pragma unroll
            for (int i = 0; i < 4; i++)
                #pragma unroll
                for (int j = 0; j < 4; j++)
                    acc[i][j] = fmaf(a[i], bv_[j], acc[i][j]);
        }
        __syncthreads();
    }

    #pragma unroll
    for (int i = 0; i < 4; i++) {
        int o = o0 + ty * 4 + i;
        if (o < O) {
            float bo = bias[o];
            __nv_bfloat16 h[4], l[4];
            #pragma unroll
            for (int j = 0; j < 4; j++)
                split_bf16(acc[i][j] + bo, h[j], l[j]);
            size_t base = (size_t)b * O * HW + (size_t)o * HW + n0 + tx * 4;
            *reinterpret_cast<__nv_bfloat162*>(&yh[base])     = __nv_bfloat162(h[0], h[1]);
            *reinterpret_cast<__nv_bfloat162*>(&yh[base + 2]) = __nv_bfloat162(h[2], h[3]);
            *reinterpret_cast<__nv_bfloat162*>(&yl[base])     = __nv_bfloat162(l[0], l[1]);
            *reinterpret_cast<__nv_bfloat162*>(&yl[base + 2]) = __nv_bfloat162(l[2], l[3]);
        }
    }
}

// ---------------------------------------------------------------------------
// mma / ldmatrix helpers
// ---------------------------------------------------------------------------
__device__ __forceinline__ void mma16816(float* c, const unsigned* a, const unsigned* b)
{
    asm volatile(
        "mma.sync.aligned.m16n8k16.row.col.f32.bf16.bf16.f32 "
        "{%0,%1,%2,%3}, {%4,%5,%6,%7}, {%8,%9}, {%0,%1,%2,%3};\n"
        : "+f"(c[0]), "+f"(c[1]), "+f"(c[2]), "+f"(c[3])
        : "r"(a[0]), "r"(a[1]), "r"(a[2]), "r"(a[3]), "r"(b[0]), "r"(b[1]));
}

__device__ __forceinline__ void ldm_x4(unsigned* r, const void* p)
{
    unsigned addr = (unsigned)__cvta_generic_to_shared(p);
    asm volatile("ldmatrix.sync.aligned.m8n8.x4.shared.b16 {%0,%1,%2,%3}, [%4];\n"
                 : "=r"(r[0]), "=r"(r[1]), "=r"(r[2]), "=r"(r[3]) : "r"(addr));
}

__device__ __forceinline__ void ldm_x4_trans(unsigned* r, const void* p)
{
    unsigned addr = (unsigned)__cvta_generic_to_shared(p);
    asm volatile("ldmatrix.sync.aligned.m8n8.x4.trans.shared.b16 {%0,%1,%2,%3}, [%4];\n"
                 : "=r"(r[0]), "=r"(r[1]), "=r"(r[2]), "=r"(r[3]) : "r"(addr));
}

// ---------------------------------------------------------------------------
// scores[b,n,m] = sum_c k[b,c,n]*q[b,c,m] on tensor cores (3-term bf16 split).
// (unchanged from R8 — 70us, near the 256MB write floor)
// ---------------------------------------------------------------------------
__global__ __launch_bounds__(256)
void scores_mma_kernel(float* __restrict__ attn)
{
    const int b  = blockIdx.z;
    const int n0 = blockIdx.y * 128;
    const int m0 = blockIdx.x * 128;

    __shared__ __nv_bfloat16 Ks_hi[32][136];
    __shared__ __nv_bfloat16 Ks_lo[32][136];
    __shared__ __nv_bfloat16 Qs_hi[32][136];
    __shared__ __nv_bfloat16 Qs_lo[32][136];

    const int t = threadIdx.x;
    const __nv_bfloat16* kh = g_kh + (size_t)b * CO * HW;
    const __nv_bfloat16* kl = g_kl + (size_t)b * CO * HW;
    const __nv_bfloat16* qh = g_qh + (size_t)b * CO * HW;
    const __nv_bfloat16* ql = g_ql + (size_t)b * CO * HW;

    #pragma unroll
    for (int e = 0; e < 2; e++) {
        int idx = t + e * 256;
        int r   = idx >> 4;
        int g   = (idx & 15) * 8;
        *reinterpret_cast<uint4*>(&Ks_hi[r][g]) = *reinterpret_cast<const uint4*>(&kh[(size_t)r * HW + n0 + g]);
        *reinterpret_cast<uint4*>(&Ks_lo[r][g]) = *reinterpret_cast<const uint4*>(&kl[(size_t)r * HW + n0 + g]);
        *reinterpret_cast<uint4*>(&Qs_hi[r][g]) = *reinterpret_cast<const uint4*>(&qh[(size_t)r * HW + m0 + g]);
        *reinterpret_cast<uint4*>(&Qs_lo[r][g]) = *reinterpret_cast<const uint4*>(&ql[(size_t)r * HW + m0 + g]);
    }
    __syncthreads();

    const int lane = t & 31;
    const int wid  = t >> 5;
    const int wm   = wid >> 2;
    const int wn   = wid & 3;

    float c[4][4][4];
    #pragma unroll
    for (int i = 0; i < 4; i++)
        #pragma unroll
        for (int j = 0; j < 4; j++)
            #pragma unroll
            for (int e = 0; e < 4; e++) c[i][j][e] = 0.f;

    #pragma unroll
    for (int s = 0; s < 2; s++) {
        unsigned ah[4][4], al[4][4], tmp[4];
        #pragma unroll
        for (int mi = 0; mi < 4; mi++) {
            int cr = s * 16 + (lane & 15);
            int nc = wm * 64 + mi * 16 + (lane >> 4) * 8;
            ldm_x4_trans(tmp, &Ks_hi[cr][nc]);
            ah[mi][0] = tmp[0]; ah[mi][1] = tmp[2]; ah[mi][2] = tmp[1]; ah[mi][3] = tmp[3];
            ldm_x4_trans(tmp, &Ks_lo[cr][nc]);
            al[mi][0] = tmp[0]; al[mi][1] = tmp[2]; al[mi][2] = tmp[1]; al[mi][3] = tmp[3];
        }
        unsigned bh[2][4], bl[2][4];
        #pragma unroll
        for (int nj = 0; nj < 2; nj++) {
            int cr = s * 16 + (lane & 15);
            int mc = wn * 32 + nj * 16 + (lane >> 4) * 8;
            ldm_x4_trans(bh[nj], &Qs_hi[cr][mc]);
            ldm_x4_trans(bl[nj], &Qs_lo[cr][mc]);
        }
        #pragma unroll
        for (int mi = 0; mi < 4; mi++) {
            #pragma unroll
            for (int nt = 0; nt < 4; nt++) {
                const unsigned* bfh = &bh[nt >> 1][(nt & 1) * 2];
                const unsigned* bfl = &bl[nt >> 1][(nt & 1) * 2];
                mma16816(c[mi][nt], ah[mi], bfh);
                mma16816(c[mi][nt], al[mi], bfh);
                mma16816(c[mi][nt], ah[mi], bfl);
            }
        }
    }

    float* S = attn + (size_t)b * HW * HW;
    #pragma unroll
    for (int mi = 0; mi < 4; mi++) {
        #pragma unroll
        for (int nt = 0; nt < 4; nt++) {
            int r   = n0 + wm * 64 + mi * 16 + (lane >> 2);
            int col = m0 + wn * 32 + nt * 8 + (lane & 3) * 2;
            const float* cc = c[mi][nt];
            *reinterpret_cast<float2*>(&S[(size_t)r * HW + col])       = make_float2(cc[0], cc[1]);
            *reinterpret_cast<float2*>(&S[(size_t)(r + 8) * HW + col]) = make_float2(cc[2], cc[3]);
        }
    }
}

// ---------------------------------------------------------------------------
// In-place row softmax (fp32 only — 512MB total traffic, no bf16 side-writes).
// ---------------------------------------------------------------------------
__global__ __launch_bounds__(256)
void softmax_kernel(float* __restrict__ attn)
{
    float* p = attn + (size_t)blockIdx.x * HW;
    const int t = threadIdx.x;

    float4 v[4];
    float mx = -1e30f;
    #pragma unroll
    for (int w = 0; w < 4; w++) {
        v[w] = *reinterpret_cast<const float4*>(&p[4 * (t + w * 256)]);
        mx = fmaxf(mx, fmaxf(fmaxf(v[w].x, v[w].y), fmaxf(v[w].z, v[w].w)));
    }

    __shared__ float warp_red[8];
    __shared__ float bcast;

    #pragma unroll
    for (int off = 16; off > 0; off >>= 1)
        mx = fmaxf(mx, __shfl_xor_sync(0xffffffffu, mx, off));
    if ((t & 31) == 0) warp_red[t >> 5] = mx;
    __syncthreads();
    if (t == 0) {
        float m = warp_red[0];
        #pragma unroll
        for (int w = 1; w < 8; w++) m = fmaxf(m, warp_red[w]);
        bcast = m;
    }
    __syncthreads();
    mx = bcast;
    __syncthreads();

    float s = 0.f;
    #pragma unroll
    for (int w = 0; w < 4; w++) {
        v[w].x = __expf(v[w].x - mx);
        v[w].y = __expf(v[w].y - mx);
        v[w].z = __expf(v[w].z - mx);
        v[w].w = __expf(v[w].w - mx);
        s += v[w].x + v[w].y + v[w].z + v[w].w;
    }

    #pragma unroll
    for (int off = 16; off > 0; off >>= 1)
        s += __shfl_xor_sync(0xffffffffu, s, off);
    if ((t & 31) == 0) warp_red[t >> 5] = s;
    __syncthreads();
    if (t == 0) {
        float tot = warp_red[0];
        #pragma unroll
        for (int w = 1; w < 8; w++) tot += warp_red[w];
        bcast = 1.0f / tot;
    }
    __syncthreads();
    float inv = bcast;

    #pragma unroll
    for (int w = 0; w < 4; w++) {
        v[w].x *= inv; v[w].y *= inv; v[w].z *= inv; v[w].w *= inv;
        *reinterpret_cast<float4*>(&p[4 * (t + w * 256)]) = v[w];
    }
}

// ---------------------------------------------------------------------------
// Tensor-core AV (R8 tile config — best measured). B (attn) is loaded as
// fp32 and hi/lo-split in registers before the smem store; smem layout,
// ldmatrix fragments and mma stream are byte-identical to R8.
// out[b,c,m] = gamma * sum_n v[b,c,n]*attn[b,n,m] + x[b,c,m]
// Block 128(c) x 128(m), BK=32, 8 warps, warp tile 64x32, register prefetch.
// ---------------------------------------------------------------------------
__global__ __launch_bounds__(256)
void av_mma_kernel(const float* __restrict__ attn, const float* __restrict__ x,
                   const float* __restrict__ gamma, float* __restrict__ out)
{
    const int b  = blockIdx.z;
    const int c0 = blockIdx.y * 128;
    const int m0 = blockIdx.x * 128;

    __shared__ __nv_bfloat16 As_hi[128][40];
    __shared__ __nv_bfloat16 As_lo[128][40];
    __shared__ __nv_bfloat16 Bs_hi[32][136];
    __shared__ __nv_bfloat16 Bs_lo[32][136];

    const __nv_bfloat16* Ah = g_vh + (size_t)b * CC * HW;
    const __nv_bfloat16* Al = g_vl + (size_t)b * CC * HW;
    const float*         Bf = attn + (size_t)b * HW * HW;   // fp32 attn

    const int t    = threadIdx.x;
    const int lane = t & 31;
    const int wid  = t >> 5;
    const int wm   = wid >> 2;
    const int wn   = wid & 3;

    // A: 128x32 bf16, uint4 = 8 bf16; 2 per thread
    const int a_row = t >> 2;                 // 0..63 (+64)
    const int a_kc  = (t & 3) * 8;
    // B: 32x128 fp32, uint4 = 4 floats; 4 per thread
    const int b_row = t >> 3;                 // 0..31
    const int b_c4  = (t & 7) * 4;            // float col base, +p*32

    float c[4][4][4];
    #pragma unroll
    for (int i = 0; i < 4; i++)
        #pragma unroll
        for (int j = 0; j < 4; j++)
            #pragma unroll
            for (int e = 0; e < 4; e++) c[i][j][e] = 0.f;

    uint4 pa_h[2], pa_l[2];
    float4 pb[4];
    #pragma unroll
    for (int e = 0; e < 2; e++) {
        pa_h[e] = *reinterpret_cast<const uint4*>(&Ah[(size_t)(c0 + a_row + e * 64) * HW + a_kc]);
        pa_l[e] = *reinterpret_cast<const uint4*>(&Al[(size_t)(c0 + a_row + e * 64) * HW + a_kc]);
    }
    #pragma unroll
    for (int p = 0; p < 4; p++)
        pb[p] = *reinterpret_cast<const float4*>(&Bf[(size_t)b_row * HW + m0 + b_c4 + p * 32]);

    for (int k0 = 0; k0 < HW; k0 += 32) {
        #pragma unroll
        for (int e = 0; e < 2; e++) {
            *reinterpret_cast<uint4*>(&As_hi[a_row + e * 64][a_kc]) = pa_h[e];
            *reinterpret_cast<uint4*>(&As_lo[a_row + e * 64][a_kc]) = pa_l[e];
        }
        #pragma unroll
        for (int p = 0; p < 4; p++) {
            int col = b_c4 + p * 32;
            const float* f = reinterpret_cast<const float*>(&pb[p]);
            __nv_bfloat16 h0, l0, h1, l1, h2, l2, h3, l3;
            split_bf16(f[0], h0, l0);
            split_bf16(f[1], h1, l1);
            split_bf16(f[2], h2, l2);
            split_bf16(f[3], h3, l3);
            *reinterpret_cast<__nv_bfloat162*>(&Bs_hi[b_row][col])     = __nv_bfloat162(h0, h1);
            *reinterpret_cast<__nv_bfloat162*>(&Bs_hi[b_row][col + 2]) = __nv_bfloat162(h2, h3);
            *reinterpret_cast<__nv_bfloat162*>(&Bs_lo[b_row][col])     = __nv_bfloat162(l0, l1);
            *reinterpret_cast<__nv_bfloat162*>(&Bs_lo[b_row][col + 2]) = __nv_bfloat162(l2, l3);
        }
        __syncthreads();

        int kn = (k0 + 32 < HW) ? (k0 + 32) : 0;
        #pragma unroll
        for (int e = 0; e < 2; e++) {
            pa_h[e] = *reinterpret_cast<const uint4*>(&Ah[(size_t)(c0 + a_row + e * 64) * HW + kn + a_kc]);
            pa_l[e] = *reinterpret_cast<const uint4*>(&Al[(size_t)(c0 + a_row + e * 64) * HW + kn + a_kc]);
        }
        #pragma unroll
        for (int p = 0; p < 4; p++)
            pb[p] = *reinterpret_cast<const float4*>(&Bf[(size_t)(kn + b_row) * HW + m0 + b_c4 + p * 32]);

        #pragma unroll
        for (int s = 0; s < 2; s++) {
            unsigned ah[4][4], al[4][4];
            #pragma unroll
            for (int mi = 0; mi < 4; mi++) {
                int ar = wm * 64 + mi * 16 + (lane & 15);
                int ac = s * 16 + (lane >> 4) * 8;
                ldm_x4(ah[mi], &As_hi[ar][ac]);
                ldm_x4(al[mi], &As_lo[ar][ac]);
            }
            unsigned bh[2][4], bl[2][4];
            #pragma unroll
            for (int nj = 0; nj < 2; nj++) {
                int br = s * 16 + (lane & 15);
                int bc = wn * 32 + nj * 16 + (lane >> 4) * 8;
                ldm_x4_trans(bh[nj], &Bs_hi[br][bc]);
                ldm_x4_trans(bl[nj], &Bs_lo[br][bc]);
            }
            #pragma unroll
            for (int mi = 0; mi < 4; mi++) {
                #pragma unroll
                for (int nt = 0; nt < 4; nt++) {
                    const unsigned* bfh = &bh[nt >> 1][(nt & 1) * 2];
                    const unsigned* bfl = &bl[nt >> 1][(nt & 1) * 2];
                    mma16816(c[mi][nt], ah[mi], bfh);   // hi*hi
                    mma16816(c[mi][nt], al[mi], bfh);   // lo*hi
                    mma16816(c[mi][nt], ah[mi], bfl);   // hi*lo
                }
            }
        }
        __syncthreads();
    }

    const float g = gamma[0];
    const float* xb = x   + (size_t)b * CC * HW;
    float*       ob = out + (size_t)b * CC * HW;
    #pragma unroll
    for (int mi = 0; mi < 4; mi++) {
        #pragma unroll
        for (int nt = 0; nt < 4; nt++) {
            int r   = c0 + wm * 64 + mi * 16 + (lane >> 2);
            int col = m0 + wn * 32 + nt * 8 + (lane & 3) * 2;
            const float* cc = c[mi][nt];
            size_t i0 = (size_t)r * HW + col;
            float2 x0 = *reinterpret_cast<const float2*>(&xb[i0]);
            float2 o0;
            o0.x = fmaf(g, cc[0], x0.x);
            o0.y = fmaf(g, cc[1], x0.y);
            *reinterpret_cast<float2*>(&ob[i0]) = o0;
            size_t i1 = (size_t)(r + 8) * HW + col;
            float2 x1 = *reinterpret_cast<const float2*>(&xb[i1]);
            float2 o1;
            o1.x = fmaf(g, cc[2], x1.x);
            o1.y = fmaf(g, cc[3], x1.y);
            *reinterpret_cast<float2*>(&ob[i1]) = o1;
        }
    }
}

// ---------------------------------------------------------------------------
extern "C" void kernel_launch(void* const* d_in, const int* in_sizes, int n_in,
                              void* d_out, int out_size)
{
    (void)in_sizes; (void)n_in; (void)out_size;
    const float* x     = (const float*)d_in[0];
    const float* Wq    = (const float*)d_in[1];
    const float* bq    = (const float*)d_in[2];
    const float* Wk    = (const float*)d_in[3];
    const float* bk    = (const float*)d_in[4];
    const float* Wv    = (const float*)d_in[5];
    const float* bv    = (const float*)d_in[6];
    const float* gamma = (const float*)d_in[7];

    float* out  = (float*)d_out;
    float* attn = out + (size_t)OUT_ELEMS;

    __nv_bfloat16 *qh, *ql, *kh, *kl, *vh, *vl;
    cudaGetSymbolAddress((void**)&qh, g_qh);
    cudaGetSymbolAddress((void**)&ql, g_ql);
    cudaGetSymbolAddress((void**)&kh, g_kh);
    cudaGetSymbolAddress((void**)&kl, g_kl);
    cudaGetSymbolAddress((void**)&vh, g_vh);
    cudaGetSymbolAddress((void**)&vl, g_vl);

    // QKV projections -> bf16 hi/lo
    {
        dim3 blk(256);
        dim3 grid_qk(HW / 64, 1, BB);
        dim3 grid_v (HW / 64, CC / 64, BB);
        conv1x1_kernel<<<grid_qk, blk>>>(x, Wq, bq, qh, ql, CO);
        conv1x1_kernel<<<grid_qk, blk>>>(x, Wk, bk, kh, kl, CO);
        conv1x1_kernel<<<grid_v,  blk>>>(x, Wv, bv, vh, vl, CC);
    }

    // scores = K^T Q on tensor cores -> fp32 scores in attn region
    {
        dim3 blk(256);
        dim3 grid(HW / 128, HW / 128, BB);
        scores_mma_kernel<<<grid, blk>>>(attn);
    }

    // in-place row softmax (fp32 only)
    softmax_kernel<<<BB * HW, 256>>>(attn);

    // out = gamma * (V @ attn) + x on tensor cores (B split in registers)
    {
        dim3 blk(256);
        dim3 grid(HW / 128, CC / 128, BB);
        av_mma_kernel<<<grid, blk>>>(attn, x, gamma, out);
    }
}